// round 14
// baseline (speedup 1.0000x reference)
#include <cuda_runtime.h>

#define HT 160
#define WDx 160
#define HWPIX 25600
#define NB 2
#define NPIX (NB * HWPIX)
#define CCH 64
#define NSETC 32

typedef unsigned long long ull;

__device__ __forceinline__ ull pack2(float a, float b) {
    ull r; asm("mov.b64 %0, {%1, %2};" : "=l"(r) : "f"(a), "f"(b)); return r;
}
__device__ __forceinline__ ull dup2(float a) {
    ull r; asm("mov.b64 %0, {%1, %1};" : "=l"(r) : "f"(a)); return r;
}
__device__ __forceinline__ ull fma2(ull a, ull b, ull c) {
    ull r; asm("fma.rn.f32x2 %0, %1, %2, %3;" : "=l"(r) : "l"(a), "l"(b), "l"(c)); return r;
}
__device__ __forceinline__ ull add2(ull a, ull b) {
    ull r; asm("add.rn.f32x2 %0, %1, %2;" : "=l"(r) : "l"(a), "l"(b)); return r;
}

// ---------------- scratch (device globals) ---------------------------------
__device__ float g_x[NPIX * CCH];
__device__ float g_att[NPIX * NSETC];
__device__ float g_u1[NPIX * CCH];
__device__ float g_uf[NPIX * CCH];
__device__ float g_z[NPIX * CCH];
__device__ float g_y[NPIX * CCH];
__device__ float g_gate[NPIX * CCH];
__device__ float g_xmean[NB * CCH];
__device__ float g_sca[NB * CCH];
__device__ ull   g_kbwT2[16 * 37 * 128];
__device__ int   g_ctr;

// ---------------- K0: prep kb weights (pair-interleaved, conflict-free) ----
// slot = jh2*64 + (jj>>1)*32 + m_blk*2 + (jj&1),  j = jh2*4 + jj, m = m_blk*8 + j
__global__ void kbw_prep_kernel(const float* __restrict__ kb_w,
                                const float* __restrict__ kb_b) {
    int idx = blockIdx.x * 256 + threadIdx.x;
    if (idx >= 16 * 37 * 128) return;
    int slot = idx & 127;
    int k = (idx >> 7) % 37;
    int g = idx / (37 * 128);
    int jh2 = slot >> 6;
    int r = slot & 63;
    int pr = r >> 5;
    int r2 = r & 31;
    int mb = r2 >> 1, lo = r2 & 1;
    int j = jh2 * 4 + pr * 2 + lo;
    int m = mb * 8 + j;
    int o = m >> 5, n = m & 31;
    float v = (k < 36) ? kb_w[n * 2304 + g * 144 + o * 36 + k]
                       : kb_b[n * 64 + g * 4 + o];
    g_kbwT2[idx] = dup2(v);
}

// ---------------- K1: fused LN1 + conv1x1a (per-thread) --------------------
__global__ void ln1_c11a_kernel(const float* __restrict__ inp,
                                const float* __restrict__ lnw,
                                const float* __restrict__ lnb,
                                const float* __restrict__ cw,
                                const float* __restrict__ cb) {
    __shared__ float ws[4096];
    __shared__ float bs[64], lw[64], lb[64];
    for (int i = threadIdx.x; i < 4096; i += blockDim.x) ws[i] = cw[i];
    if (threadIdx.x < 64) {
        bs[threadIdx.x] = cb[threadIdx.x];
        lw[threadIdx.x] = lnw[threadIdx.x];
        lb[threadIdx.x] = lnb[threadIdx.x];
    }
    __syncthreads();
    int p = blockIdx.x * blockDim.x + threadIdx.x;
    if (p >= NPIX) return;
    int bi = p / HWPIX, hw = p - bi * HWPIX;
    const float* src = inp + (size_t)bi * CCH * HWPIX + hw;
    float v[64];
    float s = 0.f;
#pragma unroll
    for (int c = 0; c < 64; c++) { v[c] = src[c * HWPIX]; s += v[c]; }
    float mu = s * (1.f / 64.f);
    float q = 0.f;
#pragma unroll
    for (int c = 0; c < 64; c++) { float d = v[c] - mu; q += d * d; }
    float rinv = rsqrtf(q * (1.f / 64.f) + 1e-6f);
    float* gx = g_x + (size_t)bi * CCH * HWPIX + hw;
#pragma unroll
    for (int c = 0; c < 64; c++) {
        v[c] = (v[c] - mu) * rinv * lw[c] + lb[c];
        gx[c * HWPIX] = v[c];
    }
    float* dst = g_u1 + (size_t)bi * CCH * HWPIX + hw;
#pragma unroll 4
    for (int o = 0; o < 64; o++) {
        float a = bs[o];
        const float4* wp = (const float4*)&ws[o * 64];
#pragma unroll
        for (int i4 = 0; i4 < 16; i4++) {
            float4 wv = wp[i4];
            a += wv.x * v[4 * i4] + wv.y * v[4 * i4 + 1] +
                 wv.z * v[4 * i4 + 2] + wv.w * v[4 * i4 + 3];
        }
        dst[o * HWPIX] = a;
    }
}

// ---------------- K2: fused pooled mean + sca (last-block pattern) ---------
__global__ void mean_sca_kernel(const float* __restrict__ w, const float* __restrict__ b) {
    int bc = blockIdx.x;
    const float* src = g_x + (size_t)bc * HWPIX;
    float s = 0.f;
    for (int i = threadIdx.x; i < HWPIX; i += blockDim.x) s += src[i];
#pragma unroll
    for (int o = 16; o > 0; o >>= 1) s += __shfl_down_sync(0xffffffffu, s, o);
    __shared__ float red[16];
    __shared__ int lastf;
    if ((threadIdx.x & 31) == 0) red[threadIdx.x >> 5] = s;
    __syncthreads();
    if (threadIdx.x == 0) {
        float t = 0.f;
        for (int i = 0; i < (int)(blockDim.x >> 5); i++) t += red[i];
        g_xmean[bc] = t * (1.f / HWPIX);
        __threadfence();
        lastf = (atomicAdd(&g_ctr, 1) == (int)gridDim.x - 1);
    }
    __syncthreads();
    if (lastf) {
        int t = threadIdx.x;
        if (t < NB * CCH) {
            int bi = t >> 6, c = t & 63;
            float a = b[c];
#pragma unroll
            for (int k = 0; k < 64; k++) a += w[c * 64 + k] * g_xmean[bi * 64 + k];
            g_sca[t] = a;
        }
        if (t == 0) g_ctr = 0;
    }
}

// ---------------- K4: COMBINED att (blocks 0..399) + uf (400..1199) --------
__global__ void __launch_bounds__(256, 2)
attuf_kernel(const float* __restrict__ c2a_w, const float* __restrict__ c2a_b,
             const float* __restrict__ c2b_w, const float* __restrict__ c2b_b,
             const float* __restrict__ attgamma,
             const float* __restrict__ w5, const float* __restrict__ b5) {
    __shared__ float smA[576 + 32 + 512 + 32 + 32];  // wa|ba|wbT|bb|ag
    __shared__ float attp[32 * 129];
    __shared__ float ws[1600];
    __shared__ float bs[16];
    int tid = threadIdx.x;
    if (blockIdx.x < 400) {
        // ------------------- attention path (j-split) ----------------------
        float* wa  = smA;
        float* ba  = smA + 576;
        float* wbT = smA + 608;
        float* bb  = smA + 1120;
        float* ag  = smA + 1152;
        for (int i = tid; i < 576; i += 256) wa[i] = c2a_w[i];
        if (tid < 32) {
            ba[tid] = c2a_b[tid];
            bb[tid] = c2b_b[tid];
            ag[tid] = attgamma[tid];
        }
        for (int i = tid; i < 512; i += 256) {
            int j = i >> 5, n = i & 31;
            wbT[i] = c2b_w[n * 16 + j];
        }
        __syncthreads();
        int pl = tid & 127, jh = tid >> 7;
        int p = blockIdx.x * 128 + pl;
        int bi = p / HWPIX, hw = p - bi * HWPIX;
        int h = hw / WDx, w = hw - h * WDx;
        const float* xb = g_x + (size_t)bi * CCH * HWPIX;
        float att_acc[32];
#pragma unroll
        for (int n = 0; n < 32; n++) att_acc[n] = 0.f;
        int j0 = jh * 8;
#pragma unroll
        for (int jl = 0; jl < 8; jl++) {
            int j = j0 + jl;
            float t0 = ba[j], t1 = ba[j + 16];
#pragma unroll
            for (int l = 0; l < 2; l++) {
                const float* xp0 = xb + (2 * j + l) * HWPIX;
                const float* xp1 = xb + (2 * (j + 16) + l) * HWPIX;
#pragma unroll
                for (int dy = 0; dy < 3; dy++) {
                    int hy = h + dy - 1;
                    bool vy = ((unsigned)hy < HT);
#pragma unroll
                    for (int dx = 0; dx < 3; dx++) {
                        int wx = w + dx - 1;
                        bool ok = vy && ((unsigned)wx < WDx);
                        int off = hy * WDx + wx;
                        float x0 = ok ? xp0[off] : 0.f;
                        float x1 = ok ? xp1[off] : 0.f;
                        t0 += wa[j * 18 + l * 9 + dy * 3 + dx] * x0;
                        t1 += wa[(j + 16) * 18 + l * 9 + dy * 3 + dx] * x1;
                    }
                }
            }
            float gj = t0 * t1;
            const float4* wp = (const float4*)&wbT[j * 32];
#pragma unroll
            for (int n4 = 0; n4 < 8; n4++) {
                float4 wv = wp[n4];
                att_acc[4 * n4 + 0] += wv.x * gj;
                att_acc[4 * n4 + 1] += wv.y * gj;
                att_acc[4 * n4 + 2] += wv.z * gj;
                att_acc[4 * n4 + 3] += wv.w * gj;
            }
        }
        if (jh == 1) {
#pragma unroll
            for (int n = 0; n < 32; n++) attp[n * 129 + pl] = att_acc[n];
        }
        __syncthreads();
        if (jh == 0) {
            float* dst = g_att + (size_t)bi * NSETC * HWPIX + hw;
#pragma unroll
            for (int n = 0; n < 32; n++)
                dst[n * HWPIX] = (att_acc[n] + attp[n * 129 + pl] + bb[n]) * ag[n];
        }
    } else {
        // ------------------- grouped 5x5 conv path -------------------------
        int bx = blockIdx.x - 400;          // 0..799
        int g0 = (bx / 200) * 4;
        int pblk = bx % 200;
        for (int i = tid; i < 1600; i += 256) {
            int oc = i & 3;
            int r = i >> 2;
            int gl = r / 100;
            int r2 = r - gl * 100;
            int ic = r2 / 25, kk = r2 - ic * 25;
            ws[i] = w5[(((g0 + gl) * 4 + oc) * 4 + ic) * 25 + kk];
        }
        if (tid < 16) bs[tid] = b5[g0 * 4 + tid];
        __syncthreads();
        int p = pblk * 256 + tid;
        int bi = p / HWPIX, hw = p - bi * HWPIX;
        int h = hw / WDx, w = hw - h * WDx;
        const float* ub = g_u1 + (size_t)bi * CCH * HWPIX;
        float* dst = g_uf + (size_t)bi * CCH * HWPIX + hw;
#pragma unroll
        for (int gl = 0; gl < 4; gl++) {
            int g = g0 + gl;
            float a0 = bs[gl * 4 + 0], a1 = bs[gl * 4 + 1], a2 = bs[gl * 4 + 2], a3 = bs[gl * 4 + 3];
            const float* gin = ub + (g * 4) * HWPIX;
#pragma unroll
            for (int dy = 0; dy < 5; dy++) {
                int hy = h + dy - 2;
                bool vy = ((unsigned)hy < HT);
#pragma unroll
                for (int dx = 0; dx < 5; dx++) {
                    int wx = w + dx - 2;
                    bool ok = vy && ((unsigned)wx < WDx);
                    int off = hy * WDx + wx;
                    int kk = dy * 5 + dx;
#pragma unroll
                    for (int ic = 0; ic < 4; ic++) {
                        float v = ok ? gin[ic * HWPIX + off] : 0.f;
                        const float4 wv = *(const float4*)&ws[(gl * 100 + ic * 25 + kk) * 4];
                        a0 += wv.x * v; a1 += wv.y * v; a2 += wv.z * v; a3 += wv.w * v;
                    }
                }
            }
            dst[(g * 4 + 0) * HWPIX] = a0;
            dst[(g * 4 + 1) * HWPIX] = a1;
            dst[(g * 4 + 2) * HWPIX] = a2;
            dst[(g * 4 + 3) * HWPIX] = a3;
        }
    }
}

// ---------------- K5: fused KBA (f32x2, 4m x 8pp warp footprint) -----------
#define KBA_SMEM_BYTES (37 * 128 * 8 + 37 * 64 * 8 + 32 * 65 * 8)
__global__ void __launch_bounds__(256, 3)
kba_kernel(const float* __restrict__ ga1) {
    extern __shared__ char smem[];
    ull* Ws2     = (ull*)smem;                                // [37][128] pair-interleaved
    ull* patch2s = (ull*)(smem + 37 * 128 * 8);               // [37][64]
    ull* att2s   = (ull*)(smem + 37 * 128 * 8 + 37 * 64 * 8); // [32][65]

    int tid = threadIdx.x;
    int bi  = blockIdx.x / (HWPIX / 128);
    int hw0 = (blockIdx.x % (HWPIX / 128)) * 128;
    int g0  = blockIdx.y * 4;

    for (int idx = tid; idx < 32 * 64; idx += 256) {
        int n = idx >> 6, pp = idx & 63;
        const float2 v = *(const float2*)&g_att[((size_t)bi * 32 + n) * HWPIX + hw0 + 2 * pp];
        att2s[n * 65 + pp] = pack2(v.x, v.y);
    }

    int lane  = tid & 31, wrp = tid >> 5;
    // warp footprint: 4 m_blks x 8 pixel-groups (crossbar-balanced)
    int m_blk = (wrp & 3) * 4 + (lane >> 3);
    int ppg   = (wrp >> 2) * 8 + (lane & 7);
    int pp0   = ppg * 4;
    int o_out = m_blk >> 2;        // warp-uniform (= wrp & 3)
    int n0    = (m_blk & 3) * 8;   // = (lane>>3)*8

    for (int gi = 0; gi < 4; gi++) {
        int g = g0 + gi;
        __syncthreads();
        const ull* wsrc = g_kbwT2 + (size_t)g * 37 * 128;
        for (int idx = tid; idx < 37 * 128; idx += 256) Ws2[idx] = wsrc[idx];
        for (int idx = tid; idx < 36 * 64; idx += 256) {
            int k = idx >> 6, pp = idx & 63;
            int ci = k / 9, kk = k - ci * 9;
            int dy = kk / 3, dx = kk - dy * 3;
            const float* ufc = g_uf + ((size_t)bi * 64 + g * 4 + ci) * HWPIX;
            float v0, v1;
            {
                int p = hw0 + 2 * pp;
                int h = p / WDx, w = p - h * WDx;
                int hy = h + dy - 1, wx = w + dx - 1;
                v0 = ((unsigned)hy < HT && (unsigned)wx < WDx) ? ufc[hy * WDx + wx] : 0.f;
            }
            {
                int p = hw0 + 2 * pp + 1;
                int h = p / WDx, w = p - h * WDx;
                int hy = h + dy - 1, wx = w + dx - 1;
                v1 = ((unsigned)hy < HT && (unsigned)wx < WDx) ? ufc[hy * WDx + wx] : 0.f;
            }
            patch2s[idx] = pack2(v0, v1);
        }
        if (tid < 64) patch2s[36 * 64 + tid] = pack2(1.f, 1.f);
        __syncthreads();

        ull part[4];
#pragma unroll
        for (int q = 0; q < 4; q++) part[q] = 0ull;

#pragma unroll
        for (int jh2 = 0; jh2 < 2; jh2++) {
            ull acc[4][4];
#pragma unroll
            for (int jj = 0; jj < 4; jj++)
#pragma unroll
                for (int q = 0; q < 4; q++) acc[jj][q] = 0ull;

            for (int k = 0; k < 37; k++) {
                ulonglong2 pv01 = *(const ulonglong2*)&patch2s[k * 64 + pp0];
                ulonglong2 pv23 = *(const ulonglong2*)&patch2s[k * 64 + pp0 + 2];
                const ull* wp = &Ws2[k * 128 + jh2 * 64];
                ulonglong2 w01 = *(const ulonglong2*)&wp[m_blk * 2];
                ulonglong2 w23 = *(const ulonglong2*)&wp[32 + m_blk * 2];
                acc[0][0] = fma2(w01.x, pv01.x, acc[0][0]);
                acc[0][1] = fma2(w01.x, pv01.y, acc[0][1]);
                acc[0][2] = fma2(w01.x, pv23.x, acc[0][2]);
                acc[0][3] = fma2(w01.x, pv23.y, acc[0][3]);
                acc[1][0] = fma2(w01.y, pv01.x, acc[1][0]);
                acc[1][1] = fma2(w01.y, pv01.y, acc[1][1]);
                acc[1][2] = fma2(w01.y, pv23.x, acc[1][2]);
                acc[1][3] = fma2(w01.y, pv23.y, acc[1][3]);
                acc[2][0] = fma2(w23.x, pv01.x, acc[2][0]);
                acc[2][1] = fma2(w23.x, pv01.y, acc[2][1]);
                acc[2][2] = fma2(w23.x, pv23.x, acc[2][2]);
                acc[2][3] = fma2(w23.x, pv23.y, acc[2][3]);
                acc[3][0] = fma2(w23.y, pv01.x, acc[3][0]);
                acc[3][1] = fma2(w23.y, pv01.y, acc[3][1]);
                acc[3][2] = fma2(w23.y, pv23.x, acc[3][2]);
                acc[3][3] = fma2(w23.y, pv23.y, acc[3][3]);
            }
#pragma unroll
            for (int q = 0; q < 4; q++)
#pragma unroll
                for (int jj = 0; jj < 4; jj++)
                    part[q] = fma2(att2s[(n0 + 4 * jh2 + jj) * 65 + pp0 + q],
                                   acc[jj][q], part[q]);
        }

        int c = g * 4 + o_out;
#pragma unroll
        for (int q = 0; q < 4; q++) {
            ull pr = part[q];
            pr = add2(pr, __shfl_xor_sync(0xffffffffu, pr, 8));
            pr = add2(pr, __shfl_xor_sync(0xffffffffu, pr, 16));
            if ((lane >> 3) == 0) {
                ull ufc2 = patch2s[(o_out * 9 + 4) * 64 + pp0 + q];
                ull ga2  = dup2(ga1[c]);
                ull z2 = fma2(ga2, pr, ufc2);
                float2 zo;
                asm("mov.b64 {%0, %1}, %2;" : "=f"(zo.x), "=f"(zo.y) : "l"(z2));
                *(float2*)&g_z[((size_t)bi * 64 + c) * HWPIX + hw0 + 2 * (pp0 + q)] = zo;
            }
        }
    }
}

// ---------------- K6: conv3 (1x1, input*sca) + beta residual -> g_y --------
__global__ void conv3_res_kernel(const float* __restrict__ inp,
                                 const float* __restrict__ w,
                                 const float* __restrict__ b,
                                 const float* __restrict__ beta) {
    __shared__ float ws[4096];
    __shared__ float bs[64];
    __shared__ float ss[64];
    int bi0 = (blockIdx.x * (int)blockDim.x) / HWPIX;
    for (int i = threadIdx.x; i < 4096; i += blockDim.x) ws[i] = w[i];
    if (threadIdx.x < 64) {
        bs[threadIdx.x] = b[threadIdx.x];
        ss[threadIdx.x] = g_sca[bi0 * 64 + threadIdx.x];
    }
    __syncthreads();
    int p = blockIdx.x * blockDim.x + threadIdx.x;
    if (p >= NPIX) return;
    int bi = p / HWPIX, hw = p - bi * HWPIX;
    const float* src = g_z + (size_t)bi * CCH * HWPIX + hw;
    const float* rsd = inp + (size_t)bi * CCH * HWPIX + hw;
    float xin[64];
#pragma unroll
    for (int i = 0; i < 64; i++) xin[i] = src[i * HWPIX] * ss[i];
    float* dst = g_y + (size_t)bi * CCH * HWPIX + hw;
#pragma unroll 4
    for (int o = 0; o < 64; o++) {
        float a = bs[o];
        const float4* wp = (const float4*)&ws[o * 64];
#pragma unroll
        for (int i4 = 0; i4 < 16; i4++) {
            float4 wv = wp[i4];
            a += wv.x * xin[4 * i4] + wv.y * xin[4 * i4 + 1] +
                 wv.z * xin[4 * i4 + 2] + wv.w * xin[4 * i4 + 3];
        }
        dst[o * HWPIX] = rsd[o * HWPIX] + a * beta[o];
    }
}

// ---------------- K7a: LN2 + conv4 + gate -> g_gate ------------------------
__global__ void ffn_gate_kernel(const float* __restrict__ ln2w, const float* __restrict__ ln2b,
                                const float* __restrict__ w4, const float* __restrict__ b4) {
    __shared__ float ws[8192]; // w4 [j][i]
    for (int i = threadIdx.x; i < 8192; i += blockDim.x) ws[i] = w4[i];
    __syncthreads();
    int p = blockIdx.x * blockDim.x + threadIdx.x;
    if (p >= NPIX) return;
    int bi = p / HWPIX, hw = p - bi * HWPIX;
    const float* yb = g_y + (size_t)bi * CCH * HWPIX + hw;
    float v[64];
    float s = 0.f;
#pragma unroll
    for (int c = 0; c < 64; c++) { v[c] = yb[c * HWPIX]; s += v[c]; }
    float mu = s * (1.f / 64.f);
    float q = 0.f;
#pragma unroll
    for (int c = 0; c < 64; c++) { float d = v[c] - mu; q += d * d; }
    float rinv = rsqrtf(q * (1.f / 64.f) + 1e-6f);
#pragma unroll
    for (int c = 0; c < 64; c++)
        v[c] = (v[c] - mu) * rinv * ln2w[c] + ln2b[c];
    float* dst = g_gate + (size_t)bi * CCH * HWPIX + hw;
#pragma unroll 2
    for (int j = 0; j < 64; j++) {
        float a = b4[j], bb = b4[j + 64];
        const float4* wpa = (const float4*)&ws[j * 64];
        const float4* wpb = (const float4*)&ws[(j + 64) * 64];
#pragma unroll
        for (int i4 = 0; i4 < 16; i4++) {
            float4 wva = wpa[i4];
            float4 wvb = wpb[i4];
            a  += wva.x * v[4 * i4] + wva.y * v[4 * i4 + 1] + wva.z * v[4 * i4 + 2] + wva.w * v[4 * i4 + 3];
            bb += wvb.x * v[4 * i4] + wvb.y * v[4 * i4 + 1] + wvb.z * v[4 * i4 + 2] + wvb.w * v[4 * i4 + 3];
        }
        dst[j * HWPIX] = a * bb;
    }
}

// ---------------- K7b: conv5 + gamma residual -> out ------------------------
__global__ void ffn_out_kernel(const float* __restrict__ w5, const float* __restrict__ b5,
                               const float* __restrict__ gamma, float* __restrict__ out) {
    __shared__ float ws[4096];
    __shared__ float bs[64], gs[64];
    for (int i = threadIdx.x; i < 4096; i += blockDim.x) ws[i] = w5[i];
    if (threadIdx.x < 64) { bs[threadIdx.x] = b5[threadIdx.x]; gs[threadIdx.x] = gamma[threadIdx.x]; }
    __syncthreads();
    int p = blockIdx.x * blockDim.x + threadIdx.x;
    if (p >= NPIX) return;
    int bi = p / HWPIX, hw = p - bi * HWPIX;
    const float* gb = g_gate + (size_t)bi * CCH * HWPIX + hw;
    const float* yb = g_y + (size_t)bi * CCH * HWPIX + hw;
    float xin[64];
#pragma unroll
    for (int i = 0; i < 64; i++) xin[i] = gb[i * HWPIX];
    float* dst = out + (size_t)bi * CCH * HWPIX + hw;
#pragma unroll 4
    for (int o = 0; o < 64; o++) {
        float a = bs[o];
        const float4* wp = (const float4*)&ws[o * 64];
#pragma unroll
        for (int i4 = 0; i4 < 16; i4++) {
            float4 wv = wp[i4];
            a += wv.x * xin[4 * i4] + wv.y * xin[4 * i4 + 1] +
                 wv.z * xin[4 * i4 + 2] + wv.w * xin[4 * i4 + 3];
        }
        dst[o * HWPIX] = yb[o * HWPIX] + a * gs[o];
    }
}

// ---------------------------------------------------------------------------
extern "C" void kernel_launch(void* const* d_in, const int* in_sizes, int n_in,
                              void* d_out, int out_size) {
    const float* inp      = (const float*)d_in[0];
    const float* ln1_w    = (const float*)d_in[1];
    const float* ln1_b    = (const float*)d_in[2];
    const float* ln2_w    = (const float*)d_in[3];
    const float* ln2_b    = (const float*)d_in[4];
    const float* sca_w    = (const float*)d_in[5];
    const float* sca_b    = (const float*)d_in[6];
    const float* c11a_w   = (const float*)d_in[7];
    const float* c11a_b   = (const float*)d_in[8];
    const float* c11b_w   = (const float*)d_in[9];
    const float* c11b_b   = (const float*)d_in[10];
    const float* c2a_w    = (const float*)d_in[11];
    const float* c2a_b    = (const float*)d_in[12];
    const float* c2b_w    = (const float*)d_in[13];
    const float* c2b_b    = (const float*)d_in[14];
    const float* conv3_w  = (const float*)d_in[15];
    const float* conv3_b  = (const float*)d_in[16];
    const float* conv4_w  = (const float*)d_in[17];
    const float* conv4_b  = (const float*)d_in[18];
    const float* conv5_w  = (const float*)d_in[19];
    const float* conv5_b  = (const float*)d_in[20];
    const float* kb_w     = (const float*)d_in[21];
    const float* kb_b     = (const float*)d_in[22];
    const float* ga1      = (const float*)d_in[23];
    const float* attgamma = (const float*)d_in[24];
    const float* beta     = (const float*)d_in[25];
    const float* gamma    = (const float*)d_in[26];
    float* out = (float*)d_out;

    cudaFuncSetAttribute(kba_kernel, cudaFuncAttributeMaxDynamicSharedMemorySize,
                         KBA_SMEM_BYTES);

    // launch #4 = kba_kernel (profiled)
    kbw_prep_kernel<<<(16 * 37 * 128 + 255) / 256, 256>>>(kb_w, kb_b);
    ln1_c11a_kernel<<<NPIX / 256, 256>>>(inp, ln1_w, ln1_b, c11a_w, c11a_b);
    attuf_kernel<<<1200, 256>>>(c2a_w, c2a_b, c2b_w, c2b_b, attgamma, c11b_w, c11b_b);
    {
        dim3 grid(NPIX / 128, 4);
        kba_kernel<<<grid, 256, KBA_SMEM_BYTES>>>(ga1);
    }
    mean_sca_kernel<<<NB * CCH, 512>>>(sca_w, sca_b);
    conv3_res_kernel<<<NPIX / 256, 256>>>(inp, conv3_w, conv3_b, beta);
    ffn_gate_kernel<<<NPIX / 256, 256>>>(ln2_w, ln2_b, conv4_w, conv4_b);
    ffn_out_kernel<<<NPIX / 256, 256>>>(conv5_w, conv5_b, gamma, out);
}

// round 15
// speedup vs baseline: 1.2538x; 1.2538x over previous
#include <cuda_runtime.h>

#define HT 160
#define WDx 160
#define HWPIX 25600
#define NB 2
#define NPIX (NB * HWPIX)
#define CCH 64
#define NSETC 32

typedef unsigned long long ull;

__device__ __forceinline__ ull pack2(float a, float b) {
    ull r; asm("mov.b64 %0, {%1, %2};" : "=l"(r) : "f"(a), "f"(b)); return r;
}
__device__ __forceinline__ ull dup2(float a) {
    ull r; asm("mov.b64 %0, {%1, %1};" : "=l"(r) : "f"(a)); return r;
}
__device__ __forceinline__ ull fma2(ull a, ull b, ull c) {
    ull r; asm("fma.rn.f32x2 %0, %1, %2, %3;" : "=l"(r) : "l"(a), "l"(b), "l"(c)); return r;
}
__device__ __forceinline__ ull add2(ull a, ull b) {
    ull r; asm("add.rn.f32x2 %0, %1, %2;" : "=l"(r) : "l"(a), "l"(b)); return r;
}

// ---------------- scratch (device globals) ---------------------------------
__device__ float g_x[NPIX * CCH];
__device__ float g_att[NPIX * NSETC];
__device__ float g_u1[NPIX * CCH];
__device__ float g_uf[NPIX * CCH];
__device__ float g_z[NPIX * CCH];
__device__ float g_y[NPIX * CCH];
__device__ float g_gate[NPIX * CCH];
__device__ float g_xmean[NB * CCH];
__device__ float g_sca[NB * CCH];
__device__ float g_kbwT[16 * 37 * 128];   // FLOAT weights, pair-interleaved
__device__ int   g_ctr;

// ---------------- K0: prep kb weights (pair-interleaved, float) ------------
// slot = jh2*64 + pr*32 + m_blk*2 + lo,  j = jh2*4 + pr*2 + lo, m = m_blk*8 + j
__global__ void kbw_prep_kernel(const float* __restrict__ kb_w,
                                const float* __restrict__ kb_b) {
    int idx = blockIdx.x * 256 + threadIdx.x;
    if (idx >= 16 * 37 * 128) return;
    int slot = idx & 127;
    int k = (idx >> 7) % 37;
    int g = idx / (37 * 128);
    int jh2 = slot >> 6;
    int r = slot & 63;
    int pr = r >> 5;
    int r2 = r & 31;
    int mb = r2 >> 1, lo = r2 & 1;
    int j = jh2 * 4 + pr * 2 + lo;
    int m = mb * 8 + j;
    int o = m >> 5, n = m & 31;
    float v = (k < 36) ? kb_w[n * 2304 + g * 144 + o * 36 + k]
                       : kb_b[n * 64 + g * 4 + o];
    g_kbwT[idx] = v;
}

// ---------------- K1: fused LN1 + conv1x1a (per-thread) --------------------
__global__ void ln1_c11a_kernel(const float* __restrict__ inp,
                                const float* __restrict__ lnw,
                                const float* __restrict__ lnb,
                                const float* __restrict__ cw,
                                const float* __restrict__ cb) {
    __shared__ float ws[4096];
    __shared__ float bs[64], lw[64], lb[64];
    for (int i = threadIdx.x; i < 4096; i += blockDim.x) ws[i] = cw[i];
    if (threadIdx.x < 64) {
        bs[threadIdx.x] = cb[threadIdx.x];
        lw[threadIdx.x] = lnw[threadIdx.x];
        lb[threadIdx.x] = lnb[threadIdx.x];
    }
    __syncthreads();
    int p = blockIdx.x * blockDim.x + threadIdx.x;
    if (p >= NPIX) return;
    int bi = p / HWPIX, hw = p - bi * HWPIX;
    const float* src = inp + (size_t)bi * CCH * HWPIX + hw;
    float v[64];
    float s = 0.f;
#pragma unroll
    for (int c = 0; c < 64; c++) { v[c] = src[c * HWPIX]; s += v[c]; }
    float mu = s * (1.f / 64.f);
    float q = 0.f;
#pragma unroll
    for (int c = 0; c < 64; c++) { float d = v[c] - mu; q += d * d; }
    float rinv = rsqrtf(q * (1.f / 64.f) + 1e-6f);
    float* gx = g_x + (size_t)bi * CCH * HWPIX + hw;
#pragma unroll
    for (int c = 0; c < 64; c++) {
        v[c] = (v[c] - mu) * rinv * lw[c] + lb[c];
        gx[c * HWPIX] = v[c];
    }
    float* dst = g_u1 + (size_t)bi * CCH * HWPIX + hw;
#pragma unroll 4
    for (int o = 0; o < 64; o++) {
        float a = bs[o];
        const float4* wp = (const float4*)&ws[o * 64];
#pragma unroll
        for (int i4 = 0; i4 < 16; i4++) {
            float4 wv = wp[i4];
            a += wv.x * v[4 * i4] + wv.y * v[4 * i4 + 1] +
                 wv.z * v[4 * i4 + 2] + wv.w * v[4 * i4 + 3];
        }
        dst[o * HWPIX] = a;
    }
}

// ---------------- K2: fused pooled mean + sca (last-block pattern) ---------
__global__ void mean_sca_kernel(const float* __restrict__ w, const float* __restrict__ b) {
    int bc = blockIdx.x;
    const float* src = g_x + (size_t)bc * HWPIX;
    float s = 0.f;
    for (int i = threadIdx.x; i < HWPIX; i += blockDim.x) s += src[i];
#pragma unroll
    for (int o = 16; o > 0; o >>= 1) s += __shfl_down_sync(0xffffffffu, s, o);
    __shared__ float red[16];
    __shared__ int lastf;
    if ((threadIdx.x & 31) == 0) red[threadIdx.x >> 5] = s;
    __syncthreads();
    if (threadIdx.x == 0) {
        float t = 0.f;
        for (int i = 0; i < (int)(blockDim.x >> 5); i++) t += red[i];
        g_xmean[bc] = t * (1.f / HWPIX);
        __threadfence();
        lastf = (atomicAdd(&g_ctr, 1) == (int)gridDim.x - 1);
    }
    __syncthreads();
    if (lastf) {
        int t = threadIdx.x;
        if (t < NB * CCH) {
            int bi = t >> 6, c = t & 63;
            float a = b[c];
#pragma unroll
            for (int k = 0; k < 64; k++) a += w[c * 64 + k] * g_xmean[bi * 64 + k];
            g_sca[t] = a;
        }
        if (t == 0) g_ctr = 0;
    }
}

// ---------------- K4: COMBINED att (blocks 0..399) + uf (400..1199) --------
__global__ void __launch_bounds__(256, 2)
attuf_kernel(const float* __restrict__ c2a_w, const float* __restrict__ c2a_b,
             const float* __restrict__ c2b_w, const float* __restrict__ c2b_b,
             const float* __restrict__ attgamma,
             const float* __restrict__ w5, const float* __restrict__ b5) {
    __shared__ float smA[576 + 32 + 512 + 32 + 32];  // wa|ba|wbT|bb|ag
    __shared__ float attp[32 * 129];
    __shared__ float ws[1600];
    __shared__ float bs[16];
    int tid = threadIdx.x;
    if (blockIdx.x < 400) {
        // ------------------- attention path (j-split) ----------------------
        float* wa  = smA;
        float* ba  = smA + 576;
        float* wbT = smA + 608;
        float* bb  = smA + 1120;
        float* ag  = smA + 1152;
        for (int i = tid; i < 576; i += 256) wa[i] = c2a_w[i];
        if (tid < 32) {
            ba[tid] = c2a_b[tid];
            bb[tid] = c2b_b[tid];
            ag[tid] = attgamma[tid];
        }
        for (int i = tid; i < 512; i += 256) {
            int j = i >> 5, n = i & 31;
            wbT[i] = c2b_w[n * 16 + j];
        }
        __syncthreads();
        int pl = tid & 127, jh = tid >> 7;
        int p = blockIdx.x * 128 + pl;
        int bi = p / HWPIX, hw = p - bi * HWPIX;
        int h = hw / WDx, w = hw - h * WDx;
        const float* xb = g_x + (size_t)bi * CCH * HWPIX;
        float att_acc[32];
#pragma unroll
        for (int n = 0; n < 32; n++) att_acc[n] = 0.f;
        int j0 = jh * 8;
#pragma unroll
        for (int jl = 0; jl < 8; jl++) {
            int j = j0 + jl;
            float t0 = ba[j], t1 = ba[j + 16];
#pragma unroll
            for (int l = 0; l < 2; l++) {
                const float* xp0 = xb + (2 * j + l) * HWPIX;
                const float* xp1 = xb + (2 * (j + 16) + l) * HWPIX;
#pragma unroll
                for (int dy = 0; dy < 3; dy++) {
                    int hy = h + dy - 1;
                    bool vy = ((unsigned)hy < HT);
#pragma unroll
                    for (int dx = 0; dx < 3; dx++) {
                        int wx = w + dx - 1;
                        bool ok = vy && ((unsigned)wx < WDx);
                        int off = hy * WDx + wx;
                        float x0 = ok ? xp0[off] : 0.f;
                        float x1 = ok ? xp1[off] : 0.f;
                        t0 += wa[j * 18 + l * 9 + dy * 3 + dx] * x0;
                        t1 += wa[(j + 16) * 18 + l * 9 + dy * 3 + dx] * x1;
                    }
                }
            }
            float gj = t0 * t1;
            const float4* wp = (const float4*)&wbT[j * 32];
#pragma unroll
            for (int n4 = 0; n4 < 8; n4++) {
                float4 wv = wp[n4];
                att_acc[4 * n4 + 0] += wv.x * gj;
                att_acc[4 * n4 + 1] += wv.y * gj;
                att_acc[4 * n4 + 2] += wv.z * gj;
                att_acc[4 * n4 + 3] += wv.w * gj;
            }
        }
        if (jh == 1) {
#pragma unroll
            for (int n = 0; n < 32; n++) attp[n * 129 + pl] = att_acc[n];
        }
        __syncthreads();
        if (jh == 0) {
            float* dst = g_att + (size_t)bi * NSETC * HWPIX + hw;
#pragma unroll
            for (int n = 0; n < 32; n++)
                dst[n * HWPIX] = (att_acc[n] + attp[n * 129 + pl] + bb[n]) * ag[n];
        }
    } else {
        // ------------------- grouped 5x5 conv path -------------------------
        int bx = blockIdx.x - 400;          // 0..799
        int g0 = (bx / 200) * 4;
        int pblk = bx % 200;
        for (int i = tid; i < 1600; i += 256) {
            int oc = i & 3;
            int r = i >> 2;
            int gl = r / 100;
            int r2 = r - gl * 100;
            int ic = r2 / 25, kk = r2 - ic * 25;
            ws[i] = w5[(((g0 + gl) * 4 + oc) * 4 + ic) * 25 + kk];
        }
        if (tid < 16) bs[tid] = b5[g0 * 4 + tid];
        __syncthreads();
        int p = pblk * 256 + tid;
        int bi = p / HWPIX, hw = p - bi * HWPIX;
        int h = hw / WDx, w = hw - h * WDx;
        const float* ub = g_u1 + (size_t)bi * CCH * HWPIX;
        float* dst = g_uf + (size_t)bi * CCH * HWPIX + hw;
#pragma unroll
        for (int gl = 0; gl < 4; gl++) {
            int g = g0 + gl;
            float a0 = bs[gl * 4 + 0], a1 = bs[gl * 4 + 1], a2 = bs[gl * 4 + 2], a3 = bs[gl * 4 + 3];
            const float* gin = ub + (g * 4) * HWPIX;
#pragma unroll
            for (int dy = 0; dy < 5; dy++) {
                int hy = h + dy - 2;
                bool vy = ((unsigned)hy < HT);
#pragma unroll
                for (int dx = 0; dx < 5; dx++) {
                    int wx = w + dx - 2;
                    bool ok = vy && ((unsigned)wx < WDx);
                    int off = hy * WDx + wx;
                    int kk = dy * 5 + dx;
#pragma unroll
                    for (int ic = 0; ic < 4; ic++) {
                        float v = ok ? gin[ic * HWPIX + off] : 0.f;
                        const float4 wv = *(const float4*)&ws[(gl * 100 + ic * 25 + kk) * 4];
                        a0 += wv.x * v; a1 += wv.y * v; a2 += wv.z * v; a3 += wv.w * v;
                    }
                }
            }
            dst[(g * 4 + 0) * HWPIX] = a0;
            dst[(g * 4 + 1) * HWPIX] = a1;
            dst[(g * 4 + 2) * HWPIX] = a2;
            dst[(g * 4 + 3) * HWPIX] = a3;
        }
    }
}

// ---------------- K5: fused KBA (float weights, in-register dup) -----------
#define KBA_SMEM_BYTES (37 * 128 * 4 + 37 * 64 * 8 + 32 * 65 * 8)
__global__ void __launch_bounds__(256, 3)
kba_kernel(const float* __restrict__ ga1) {
    extern __shared__ char smem[];
    float* Wsf    = (float*)smem;                              // [37][128] float
    ull* patch2s  = (ull*)(smem + 37 * 128 * 4);               // [37][64]
    ull* att2s    = (ull*)(smem + 37 * 128 * 4 + 37 * 64 * 8); // [32][65]

    int tid = threadIdx.x;
    int bi  = blockIdx.x / (HWPIX / 128);
    int hw0 = (blockIdx.x % (HWPIX / 128)) * 128;
    int g0  = blockIdx.y * 4;

    for (int idx = tid; idx < 32 * 64; idx += 256) {
        int n = idx >> 6, pp = idx & 63;
        const float2 v = *(const float2*)&g_att[((size_t)bi * 32 + n) * HWPIX + hw0 + 2 * pp];
        att2s[n * 65 + pp] = pack2(v.x, v.y);
    }

    int m_blk = tid & 15;
    int pp0   = (tid >> 4) * 4;
    int o_out = m_blk >> 2;
    int n0    = (m_blk & 3) * 8;

    for (int gi = 0; gi < 4; gi++) {
        int g = g0 + gi;
        __syncthreads();
        const float* wsrc = g_kbwT + (size_t)g * 37 * 128;
        for (int idx = tid; idx < 37 * 128; idx += 256) Wsf[idx] = wsrc[idx];
        for (int idx = tid; idx < 36 * 64; idx += 256) {
            int k = idx >> 6, pp = idx & 63;
            int ci = k / 9, kk = k - ci * 9;
            int dy = kk / 3, dx = kk - dy * 3;
            const float* ufc = g_uf + ((size_t)bi * 64 + g * 4 + ci) * HWPIX;
            float v0, v1;
            {
                int p = hw0 + 2 * pp;
                int h = p / WDx, w = p - h * WDx;
                int hy = h + dy - 1, wx = w + dx - 1;
                v0 = ((unsigned)hy < HT && (unsigned)wx < WDx) ? ufc[hy * WDx + wx] : 0.f;
            }
            {
                int p = hw0 + 2 * pp + 1;
                int h = p / WDx, w = p - h * WDx;
                int hy = h + dy - 1, wx = w + dx - 1;
                v1 = ((unsigned)hy < HT && (unsigned)wx < WDx) ? ufc[hy * WDx + wx] : 0.f;
            }
            patch2s[idx] = pack2(v0, v1);
        }
        if (tid < 64) patch2s[36 * 64 + tid] = pack2(1.f, 1.f);
        __syncthreads();

        ull part[4];
#pragma unroll
        for (int q = 0; q < 4; q++) part[q] = 0ull;

#pragma unroll
        for (int jh2 = 0; jh2 < 2; jh2++) {
            ull acc[4][4];
#pragma unroll
            for (int jj = 0; jj < 4; jj++)
#pragma unroll
                for (int q = 0; q < 4; q++) acc[jj][q] = 0ull;

            for (int k = 0; k < 37; k++) {
                ulonglong2 pv01 = *(const ulonglong2*)&patch2s[k * 64 + pp0];
                ulonglong2 pv23 = *(const ulonglong2*)&patch2s[k * 64 + pp0 + 2];
                const float* wp = &Wsf[k * 128 + jh2 * 64];
                float2 wf01 = *(const float2*)&wp[m_blk * 2];
                float2 wf23 = *(const float2*)&wp[32 + m_blk * 2];
                ull w0 = dup2(wf01.x), w1 = dup2(wf01.y);
                ull w2 = dup2(wf23.x), w3 = dup2(wf23.y);
                acc[0][0] = fma2(w0, pv01.x, acc[0][0]);
                acc[0][1] = fma2(w0, pv01.y, acc[0][1]);
                acc[0][2] = fma2(w0, pv23.x, acc[0][2]);
                acc[0][3] = fma2(w0, pv23.y, acc[0][3]);
                acc[1][0] = fma2(w1, pv01.x, acc[1][0]);
                acc[1][1] = fma2(w1, pv01.y, acc[1][1]);
                acc[1][2] = fma2(w1, pv23.x, acc[1][2]);
                acc[1][3] = fma2(w1, pv23.y, acc[1][3]);
                acc[2][0] = fma2(w2, pv01.x, acc[2][0]);
                acc[2][1] = fma2(w2, pv01.y, acc[2][1]);
                acc[2][2] = fma2(w2, pv23.x, acc[2][2]);
                acc[2][3] = fma2(w2, pv23.y, acc[2][3]);
                acc[3][0] = fma2(w3, pv01.x, acc[3][0]);
                acc[3][1] = fma2(w3, pv01.y, acc[3][1]);
                acc[3][2] = fma2(w3, pv23.x, acc[3][2]);
                acc[3][3] = fma2(w3, pv23.y, acc[3][3]);
            }
#pragma unroll
            for (int q = 0; q < 4; q++)
#pragma unroll
                for (int jj = 0; jj < 4; jj++)
                    part[q] = fma2(att2s[(n0 + 4 * jh2 + jj) * 65 + pp0 + q],
                                   acc[jj][q], part[q]);
        }

        int c = g * 4 + o_out;
#pragma unroll
        for (int q = 0; q < 4; q++) {
            ull pr = part[q];
            pr = add2(pr, __shfl_xor_sync(0xffffffffu, pr, 1));
            pr = add2(pr, __shfl_xor_sync(0xffffffffu, pr, 2));
            if ((tid & 3) == 0) {
                ull ufc2 = patch2s[(o_out * 9 + 4) * 64 + pp0 + q];
                ull ga2  = dup2(ga1[c]);
                ull z2 = fma2(ga2, pr, ufc2);
                float2 zo;
                asm("mov.b64 {%0, %1}, %2;" : "=f"(zo.x), "=f"(zo.y) : "l"(z2));
                *(float2*)&g_z[((size_t)bi * 64 + c) * HWPIX + hw0 + 2 * (pp0 + q)] = zo;
            }
        }
    }
}

// ---------------- K6: conv3 (1x1, input*sca) + beta residual -> g_y --------
__global__ void conv3_res_kernel(const float* __restrict__ inp,
                                 const float* __restrict__ w,
                                 const float* __restrict__ b,
                                 const float* __restrict__ beta) {
    __shared__ float ws[4096];
    __shared__ float bs[64];
    __shared__ float ss[64];
    int bi0 = (blockIdx.x * (int)blockDim.x) / HWPIX;
    for (int i = threadIdx.x; i < 4096; i += blockDim.x) ws[i] = w[i];
    if (threadIdx.x < 64) {
        bs[threadIdx.x] = b[threadIdx.x];
        ss[threadIdx.x] = g_sca[bi0 * 64 + threadIdx.x];
    }
    __syncthreads();
    int p = blockIdx.x * blockDim.x + threadIdx.x;
    if (p >= NPIX) return;
    int bi = p / HWPIX, hw = p - bi * HWPIX;
    const float* src = g_z + (size_t)bi * CCH * HWPIX + hw;
    const float* rsd = inp + (size_t)bi * CCH * HWPIX + hw;
    float xin[64];
#pragma unroll
    for (int i = 0; i < 64; i++) xin[i] = src[i * HWPIX] * ss[i];
    float* dst = g_y + (size_t)bi * CCH * HWPIX + hw;
#pragma unroll 4
    for (int o = 0; o < 64; o++) {
        float a = bs[o];
        const float4* wp = (const float4*)&ws[o * 64];
#pragma unroll
        for (int i4 = 0; i4 < 16; i4++) {
            float4 wv = wp[i4];
            a += wv.x * xin[4 * i4] + wv.y * xin[4 * i4 + 1] +
                 wv.z * xin[4 * i4 + 2] + wv.w * xin[4 * i4 + 3];
        }
        dst[o * HWPIX] = rsd[o * HWPIX] + a * beta[o];
    }
}

// ---------------- K7a: LN2 + conv4 + gate -> g_gate ------------------------
__global__ void ffn_gate_kernel(const float* __restrict__ ln2w, const float* __restrict__ ln2b,
                                const float* __restrict__ w4, const float* __restrict__ b4) {
    __shared__ float ws[8192]; // w4 [j][i]
    for (int i = threadIdx.x; i < 8192; i += blockDim.x) ws[i] = w4[i];
    __syncthreads();
    int p = blockIdx.x * blockDim.x + threadIdx.x;
    if (p >= NPIX) return;
    int bi = p / HWPIX, hw = p - bi * HWPIX;
    const float* yb = g_y + (size_t)bi * CCH * HWPIX + hw;
    float v[64];
    float s = 0.f;
#pragma unroll
    for (int c = 0; c < 64; c++) { v[c] = yb[c * HWPIX]; s += v[c]; }
    float mu = s * (1.f / 64.f);
    float q = 0.f;
#pragma unroll
    for (int c = 0; c < 64; c++) { float d = v[c] - mu; q += d * d; }
    float rinv = rsqrtf(q * (1.f / 64.f) + 1e-6f);
#pragma unroll
    for (int c = 0; c < 64; c++)
        v[c] = (v[c] - mu) * rinv * ln2w[c] + ln2b[c];
    float* dst = g_gate + (size_t)bi * CCH * HWPIX + hw;
#pragma unroll 2
    for (int j = 0; j < 64; j++) {
        float a = b4[j], bb = b4[j + 64];
        const float4* wpa = (const float4*)&ws[j * 64];
        const float4* wpb = (const float4*)&ws[(j + 64) * 64];
#pragma unroll
        for (int i4 = 0; i4 < 16; i4++) {
            float4 wva = wpa[i4];
            float4 wvb = wpb[i4];
            a  += wva.x * v[4 * i4] + wva.y * v[4 * i4 + 1] + wva.z * v[4 * i4 + 2] + wva.w * v[4 * i4 + 3];
            bb += wvb.x * v[4 * i4] + wvb.y * v[4 * i4 + 1] + wvb.z * v[4 * i4 + 2] + wvb.w * v[4 * i4 + 3];
        }
        dst[j * HWPIX] = a * bb;
    }
}

// ---------------- K7b: conv5 + gamma residual -> out ------------------------
__global__ void ffn_out_kernel(const float* __restrict__ w5, const float* __restrict__ b5,
                               const float* __restrict__ gamma, float* __restrict__ out) {
    __shared__ float ws[4096];
    __shared__ float bs[64], gs[64];
    for (int i = threadIdx.x; i < 4096; i += blockDim.x) ws[i] = w5[i];
    if (threadIdx.x < 64) { bs[threadIdx.x] = b5[threadIdx.x]; gs[threadIdx.x] = gamma[threadIdx.x]; }
    __syncthreads();
    int p = blockIdx.x * blockDim.x + threadIdx.x;
    if (p >= NPIX) return;
    int bi = p / HWPIX, hw = p - bi * HWPIX;
    const float* gb = g_gate + (size_t)bi * CCH * HWPIX + hw;
    const float* yb = g_y + (size_t)bi * CCH * HWPIX + hw;
    float xin[64];
#pragma unroll
    for (int i = 0; i < 64; i++) xin[i] = gb[i * HWPIX];
    float* dst = out + (size_t)bi * CCH * HWPIX + hw;
#pragma unroll 4
    for (int o = 0; o < 64; o++) {
        float a = bs[o];
        const float4* wp = (const float4*)&ws[o * 64];
#pragma unroll
        for (int i4 = 0; i4 < 16; i4++) {
            float4 wv = wp[i4];
            a += wv.x * xin[4 * i4] + wv.y * xin[4 * i4 + 1] +
                 wv.z * xin[4 * i4 + 2] + wv.w * xin[4 * i4 + 3];
        }
        dst[o * HWPIX] = yb[o * HWPIX] + a * gs[o];
    }
}

// ---------------------------------------------------------------------------
extern "C" void kernel_launch(void* const* d_in, const int* in_sizes, int n_in,
                              void* d_out, int out_size) {
    const float* inp      = (const float*)d_in[0];
    const float* ln1_w    = (const float*)d_in[1];
    const float* ln1_b    = (const float*)d_in[2];
    const float* ln2_w    = (const float*)d_in[3];
    const float* ln2_b    = (const float*)d_in[4];
    const float* sca_w    = (const float*)d_in[5];
    const float* sca_b    = (const float*)d_in[6];
    const float* c11a_w   = (const float*)d_in[7];
    const float* c11a_b   = (const float*)d_in[8];
    const float* c11b_w   = (const float*)d_in[9];
    const float* c11b_b   = (const float*)d_in[10];
    const float* c2a_w    = (const float*)d_in[11];
    const float* c2a_b    = (const float*)d_in[12];
    const float* c2b_w    = (const float*)d_in[13];
    const float* c2b_b    = (const float*)d_in[14];
    const float* conv3_w  = (const float*)d_in[15];
    const float* conv3_b  = (const float*)d_in[16];
    const float* conv4_w  = (const float*)d_in[17];
    const float* conv4_b  = (const float*)d_in[18];
    const float* conv5_w  = (const float*)d_in[19];
    const float* conv5_b  = (const float*)d_in[20];
    const float* kb_w     = (const float*)d_in[21];
    const float* kb_b     = (const float*)d_in[22];
    const float* ga1      = (const float*)d_in[23];
    const float* attgamma = (const float*)d_in[24];
    const float* beta     = (const float*)d_in[25];
    const float* gamma    = (const float*)d_in[26];
    float* out = (float*)d_out;

    cudaFuncSetAttribute(kba_kernel, cudaFuncAttributeMaxDynamicSharedMemorySize,
                         KBA_SMEM_BYTES);

    // launch #4 = kba_kernel (profiled)
    kbw_prep_kernel<<<(16 * 37 * 128 + 255) / 256, 256>>>(kb_w, kb_b);
    ln1_c11a_kernel<<<NPIX / 256, 256>>>(inp, ln1_w, ln1_b, c11a_w, c11a_b);
    attuf_kernel<<<1200, 256>>>(c2a_w, c2a_b, c2b_w, c2b_b, attgamma, c11b_w, c11b_b);
    {
        dim3 grid(NPIX / 128, 4);
        kba_kernel<<<grid, 256, KBA_SMEM_BYTES>>>(ga1);
    }
    mean_sca_kernel<<<NB * CCH, 512>>>(sca_w, sca_b);
    conv3_res_kernel<<<NPIX / 256, 256>>>(inp, conv3_w, conv3_b, beta);
    ffn_gate_kernel<<<NPIX / 256, 256>>>(ln2_w, ln2_b, conv4_w, conv4_b);
    ffn_out_kernel<<<NPIX / 256, 256>>>(conv5_w, conv5_b, gamma, out);
}